// round 6
// baseline (speedup 1.0000x reference)
#include <cuda_runtime.h>
#include <cstdint>

// Problem constants
static constexpr int BDIM = 2;
static constexpr int NC   = 16384;
static constexpr int NF   = 65536;
static constexpr int CI   = 128;
static constexpr int CO   = 128;
static constexpr int EC   = 65536;
static constexpr int EF   = 262144;
static constexpr int MROW = BDIM * NC;   // 32768 coarse rows

// Scratch (device globals; zero-initialized at module load)
__device__ float g_hb [(size_t)BDIM * NF * CO];        // s+b conv accumulator
__device__ float g_ha [(size_t)BDIM * NC * (CO / 2)];  // a-conv accumulator
__device__ int   g_invmap[NF];                         // fine -> coarse (or -1)
__device__ int   g_cntA[NF + 16];                      // [NF] = nComp
__device__ int   g_csrcC[EF];                          // compacted: coarse src (-1 ok)
__device__ int   g_cdstC[EF];                          // compacted: coarse dst (-1 ok)
__device__ int   g_cdstF[EF];                          // compacted: fine dst
__device__ float g_cs[CO];
__device__ float g_cb[CO];
__device__ float g_w1s[2 * CI * CO];                   // [W1a-W1b ; W1b] (s)
__device__ float g_w1a[2 * CI * (CO / 2)];
__device__ float g_w1b[CO * CO];                       // (64*2) x 128
__device__ float g_Ps[(size_t)MROW * CO];
__device__ float g_Qs[(size_t)MROW * CO];
__device__ float g_Pa[(size_t)MROW * (CO / 2)];
__device__ float g_Qa[(size_t)MROW * (CO / 2)];
__device__ float g_Pb[(size_t)MROW * CO];
__device__ float g_Qb[(size_t)MROW * CO];

// ---------------------------------------------------------------------------
typedef unsigned long long u64;
__device__ __forceinline__ u64 pk2(float x) {
    u64 r; asm("mov.b64 %0,{%1,%1};" : "=l"(r) : "f"(x)); return r;
}
__device__ __forceinline__ void up2(u64 v, float& x, float& y) {
    asm("mov.b64 {%0,%1},%2;" : "=f"(x), "=f"(y) : "l"(v));
}
__device__ __forceinline__ u64 fma2(u64 a, u64 b, u64 c) {
    u64 d; asm("fma.rn.f32x2 %0,%1,%2,%3;" : "=l"(d) : "l"(a), "l"(b), "l"(c)); return d;
}

// ---------------------------------------------------------------------------
__global__ void zero_kernel(float4* __restrict__ p, int n4) {
    int i = blockIdx.x * blockDim.x + threadIdx.x;
    int stride = gridDim.x * blockDim.x;
    float4 z = make_float4(0.f, 0.f, 0.f, 0.f);
    for (; i < n4; i += stride) p[i] = z;
}

__global__ void neg1_kernel(int4* __restrict__ p, int n4) {
    int i = blockIdx.x * blockDim.x + threadIdx.x;
    int stride = gridDim.x * blockDim.x;
    int4 m = make_int4(-1, -1, -1, -1);
    for (; i < n4; i += stride) p[i] = m;
}

__global__ void invmap_kernel(const int* __restrict__ idx, int* __restrict__ invmap) {
    int i = blockIdx.x * blockDim.x + threadIdx.x;
    if (i < NC) invmap[idx[i]] = i;
}

__global__ void classify_kernel(const int* __restrict__ ei, const int* __restrict__ invmap,
                                int* __restrict__ cntA, int* __restrict__ csrcC,
                                int* __restrict__ cdstC, int* __restrict__ cdstF,
                                int* __restrict__ ncomp) {
    int e = blockIdx.x * blockDim.x + threadIdx.x;
    if (e >= EF) return;
    int s = ei[e], d = ei[EF + e];
    int sc = invmap[s], dc = invmap[d];
    if (sc < 0 && dc < 0) {
        atomicAdd(&cntA[d], 1);
    } else {
        unsigned act = __activemask();
        int lane = threadIdx.x & 31;
        int rank = __popc(act & ((1u << lane) - 1));
        int leader = __ffs(act) - 1;
        int base = 0;
        if (lane == leader) base = atomicAdd(ncomp, __popc(act));
        base = __shfl_sync(act, base, leader);
        csrcC[base + rank] = sc;
        cdstC[base + rank] = dc;
        cdstF[base + rank] = d;
    }
}

// W1t: rows [0,cin) = W1a - W1b ; rows [cin,2cin) = W1b
__global__ void prepW1_kernel(const float* __restrict__ W1, float* __restrict__ W1t,
                              int cin, int cout) {
    int i = blockIdx.x * blockDim.x + threadIdx.x;
    int n = cin * cout;
    if (i >= n) return;
    float top = W1[i];
    float bot = W1[n + i];
    W1t[i]     = top - bot;
    W1t[n + i] = bot;
}

__global__ void constvec_kernel(const float* __restrict__ b1, const float* __restrict__ W2,
                                const float* __restrict__ b2, const float* __restrict__ g,
                                const float* __restrict__ bt, float* __restrict__ c) {
    int j = threadIdx.x;  // CO threads
    float acc = b2[j];
    #pragma unroll 4
    for (int k = 0; k < CO; k++) acc += fmaxf(b1[k], 0.f) * W2[k * CO + j];
    __shared__ float rs_[4], rq_[4];
    float s = acc, qv = acc * acc;
    #pragma unroll
    for (int o = 16; o; o >>= 1) {
        s  += __shfl_xor_sync(0xffffffffu, s, o);
        qv += __shfl_xor_sync(0xffffffffu, qv, o);
    }
    int warp = j >> 5, lane = j & 31;
    if (lane == 0) { rs_[warp] = s; rq_[warp] = qv; }
    __syncthreads();
    float S = 0.f, Q = 0.f;
    #pragma unroll
    for (int w = 0; w < 4; w++) { S += rs_[w]; Q += rq_[w]; }
    float mu  = S * (1.f / CO);
    float var = Q * (1.f / CO) - mu * mu;
    c[j] = (acc - mu) * rsqrtf(var + 1e-5f) * g[j] + bt[j];
}

// ---------------------------------------------------------------------------
// Node-level GEMM: R[M, COUT] = X[M, K] @ W[K, COUT]. One 32-row tile per block.
template <int K, int COUT>
__global__ void __launch_bounds__(256, 2)
nodegemm_kernel(const float* __restrict__ X, const float* __restrict__ W,
                float* __restrict__ R) {
    constexpr int PX  = K + 1;
    constexpr int JT  = COUT / 16;
    constexpr int JT2 = JT / 2;
    constexpr int NXU = K / 32;

    extern __shared__ float sm[];
    float* sW = sm;             // K*COUT
    float* sX = sW + K * COUT;  // 32*PX

    const int tid = threadIdx.x;
    const int m0  = blockIdx.x * 32;

    for (int i = tid; i < (K * COUT) / 4; i += 256)
        reinterpret_cast<float4*>(sW)[i] = reinterpret_cast<const float4*>(W)[i];
    {
        int row = tid >> 3, sub = tid & 7;
        const float4* xr = reinterpret_cast<const float4*>(X + (size_t)(m0 + row) * K);
        #pragma unroll
        for (int u = 0; u < NXU; u++) {
            float4 v = xr[sub + 8 * u];
            float* d = sX + row * PX + (sub + 8 * u) * 4;
            d[0] = v.x; d[1] = v.y; d[2] = v.z; d[3] = v.w;
        }
    }
    __syncthreads();

    const int eh = tid & 15, jg = tid >> 4, j0 = jg * JT;
    u64 acc[2][JT2];
    #pragma unroll
    for (int t = 0; t < JT2; t++) { acc[0][t] = 0ull; acc[1][t] = 0ull; }

    #pragma unroll 2
    for (int k = 0; k < K; ++k) {
        u64 w[JT2];
        if constexpr (JT2 == 4) {
            ulonglong2 w01 = *reinterpret_cast<const ulonglong2*>(&sW[k * COUT + j0]);
            ulonglong2 w23 = *reinterpret_cast<const ulonglong2*>(&sW[k * COUT + j0 + 4]);
            w[0] = w01.x; w[1] = w01.y; w[2] = w23.x; w[3] = w23.y;
        } else {
            ulonglong2 w01 = *reinterpret_cast<const ulonglong2*>(&sW[k * COUT + j0]);
            w[0] = w01.x; w[1] = w01.y;
        }
        u64 f0 = pk2(sX[eh * PX + k]);
        u64 f1 = pk2(sX[(eh + 16) * PX + k]);
        #pragma unroll
        for (int t = 0; t < JT2; t++) {
            acc[0][t] = fma2(f0, w[t], acc[0][t]);
            acc[1][t] = fma2(f1, w[t], acc[1][t]);
        }
    }

    #pragma unroll
    for (int i = 0; i < 2; i++) {
        float v[JT];
        #pragma unroll
        for (int t = 0; t < JT2; t++) up2(acc[i][t], v[2 * t], v[2 * t + 1]);
        float* rr = R + (size_t)(m0 + eh + 16 * i) * COUT + j0;
        #pragma unroll
        for (int t = 0; t < JT; t += 4)
            *reinterpret_cast<float4*>(rr + t) =
                make_float4(v[t], v[t + 1], v[t + 2], v[t + 3]);
    }
}

// ---------------------------------------------------------------------------
// a-conv edge kernel (COUT=64), unchanged structure from R5.
__global__ void __launch_bounds__(256, 2)
edgeconv64_kernel(const float* __restrict__ P, const float* __restrict__ Q,
                  const int* __restrict__ srcC, const int* __restrict__ dstC,
                  const float* __restrict__ b1, const float* __restrict__ W2,
                  const float* __restrict__ b2, const float* __restrict__ gam,
                  const float* __restrict__ bet,
                  float* __restrict__ out, int E, int NOUT) {
    constexpr int COUT = 64;
    constexpr int NE   = 64;
    constexpr int EOFF = NE / 2;
    constexpr int P2   = COUT + 2;
    constexpr int TPE  = 256 / NE;          // 4
    constexpr int NJG  = 256 / EOFF;        // 8
    constexpr int PST  = NJG + 1;
    constexpr int JTU  = 4;
    constexpr int NU   = 4;

    extern __shared__ float sm[];
    float* sW2 = sm;
    float* sb1 = sW2 + COUT * COUT;
    float* sb2 = sb1 + COUT;
    float* sg  = sb2 + COUT;
    float* sbt = sg + COUT;
    float* sF  = sbt + COUT;
    float* sPart = sF + NE * P2;
    int*  sdst = (int*)(sPart + NE * PST * 2);

    const int tid = threadIdx.x;
    const int ge  = tid / TPE;
    const int sub = tid % TPE;
    const int eh  = tid & (EOFF - 1);
    const int jg  = tid / EOFF;
    const int j0  = jg * 8;

    for (int i = tid; i < (COUT * COUT) / 4; i += 256)
        reinterpret_cast<float4*>(sW2)[i] = reinterpret_cast<const float4*>(W2)[i];
    if (tid < COUT) {
        sb1[tid] = b1[tid]; sb2[tid] = b2[tid];
        sg[tid]  = gam[tid]; sbt[tid] = bet[tid];
    }

    const int total  = 2 * E;
    const int ntiles = (total + NE - 1) / NE;

    float4 pfP[NU], pfQ[NU];
    int pdst = -1;

    auto fetch = [&](int tile) {
        pdst = -1;
        #pragma unroll
        for (int u = 0; u < NU; u++) {
            pfP[u] = make_float4(0.f, 0.f, 0.f, 0.f);
            pfQ[u] = make_float4(0.f, 0.f, 0.f, 0.f);
        }
        int gi = tile * NE + ge;
        if (tile < ntiles && gi < total) {
            int bb = (gi >= E) ? 1 : 0;
            int ee = gi - bb * E;
            int sc = srcC[ee];
            int dc = dstC[ee];
            pdst = bb * NOUT + dc;
            const float4* pr = reinterpret_cast<const float4*>(
                P + (size_t)(bb * NC + dc) * COUT);
            const float4* qr = reinterpret_cast<const float4*>(
                Q + (size_t)(bb * NC + sc) * COUT);
            #pragma unroll
            for (int u = 0; u < NU; u++) {
                pfP[u] = pr[sub + TPE * u];
                pfQ[u] = qr[sub + TPE * u];
            }
        }
    };

    fetch(blockIdx.x);

    for (int tile = blockIdx.x; tile < ntiles; tile += gridDim.x) {
        __syncthreads();
        {
            float2* frow = reinterpret_cast<float2*>(sF + ge * P2);
            #pragma unroll
            for (int u = 0; u < NU; u++) {
                int c4 = sub + TPE * u;
                float4 b = reinterpret_cast<const float4*>(sb1)[c4];
                frow[c4 * 2] = make_float2(fmaxf(pfP[u].x + pfQ[u].x + b.x, 0.f),
                                           fmaxf(pfP[u].y + pfQ[u].y + b.y, 0.f));
                frow[c4 * 2 + 1] = make_float2(fmaxf(pfP[u].z + pfQ[u].z + b.z, 0.f),
                                               fmaxf(pfP[u].w + pfQ[u].w + b.w, 0.f));
            }
            if (sub == 0) sdst[ge] = pdst;
        }
        __syncthreads();

        fetch(tile + gridDim.x);

        u64 a0[JTU], a1[JTU];
        #pragma unroll
        for (int t = 0; t < JTU; t++) {
            u64 bv = *reinterpret_cast<const u64*>(&sb2[j0 + 2 * t]);
            a0[t] = bv; a1[t] = bv;
        }
        #pragma unroll 2
        for (int k = 0; k < COUT; k += 2) {
            u64 wa[JTU], wb[JTU];
            {
                ulonglong2 t0 = *reinterpret_cast<const ulonglong2*>(&sW2[k * COUT + j0]);
                ulonglong2 t1 = *reinterpret_cast<const ulonglong2*>(&sW2[k * COUT + j0 + 4]);
                wa[0] = t0.x; wa[1] = t0.y; wa[2] = t1.x; wa[3] = t1.y;
            }
            {
                ulonglong2 t0 = *reinterpret_cast<const ulonglong2*>(&sW2[(k + 1) * COUT + j0]);
                ulonglong2 t1 = *reinterpret_cast<const ulonglong2*>(&sW2[(k + 1) * COUT + j0 + 4]);
                wb[0] = t0.x; wb[1] = t0.y; wb[2] = t1.x; wb[3] = t1.y;
            }
            float2 f0 = *reinterpret_cast<const float2*>(&sF[eh * P2 + k]);
            float2 f1 = *reinterpret_cast<const float2*>(&sF[(eh + EOFF) * P2 + k]);
            u64 x0 = pk2(f0.x), x1 = pk2(f0.y);
            u64 y0 = pk2(f1.x), y1 = pk2(f1.y);
            #pragma unroll
            for (int t = 0; t < JTU; t++) {
                a0[t] = fma2(x0, wa[t], a0[t]);
                a0[t] = fma2(x1, wb[t], a0[t]);
                a1[t] = fma2(y0, wa[t], a1[t]);
                a1[t] = fma2(y1, wb[t], a1[t]);
            }
        }

        {
            float s0 = 0.f, q0 = 0.f, s1 = 0.f, q1 = 0.f;
            #pragma unroll
            for (int t = 0; t < JTU; t++) {
                float va, vb;
                up2(a0[t], va, vb); s0 += va + vb; q0 += va * va + vb * vb;
                up2(a1[t], va, vb); s1 += va + vb; q1 += va * va + vb * vb;
            }
            float2* pp = reinterpret_cast<float2*>(sPart);
            pp[eh * PST + jg]          = make_float2(s0, q0);
            pp[(eh + EOFF) * PST + jg] = make_float2(s1, q1);
        }
        __syncthreads();

        #pragma unroll
        for (int i = 0; i < 2; i++) {
            int e = eh + EOFF * i;
            int row = sdst[e];
            const u64* acc = i ? a1 : a0;
            float s = 0.f, q = 0.f;
            const float2* pp = reinterpret_cast<const float2*>(sPart) + e * PST;
            #pragma unroll
            for (int t = 0; t < NJG; t++) { float2 v = pp[t]; s += v.x; q += v.y; }
            float mu  = s * (1.f / COUT);
            float var = q * (1.f / COUT) - mu * mu;
            float rs  = rsqrtf(var + 1e-5f);
            if (row >= 0) {
                float4 g0 = *reinterpret_cast<const float4*>(sg + j0);
                float4 g1 = *reinterpret_cast<const float4*>(sg + j0 + 4);
                float4 t0 = *reinterpret_cast<const float4*>(sbt + j0);
                float4 t1 = *reinterpret_cast<const float4*>(sbt + j0 + 4);
                float v0, v1, v2, v3, v4, v5, v6, v7;
                up2(acc[0], v0, v1); up2(acc[1], v2, v3);
                up2(acc[2], v4, v5); up2(acc[3], v6, v7);
                float4 r0, r1;
                r0.x = (v0 - mu) * rs * g0.x + t0.x;
                r0.y = (v1 - mu) * rs * g0.y + t0.y;
                r0.z = (v2 - mu) * rs * g0.z + t0.z;
                r0.w = (v3 - mu) * rs * g0.w + t0.w;
                r1.x = (v4 - mu) * rs * g1.x + t1.x;
                r1.y = (v5 - mu) * rs * g1.y + t1.y;
                r1.z = (v6 - mu) * rs * g1.z + t1.z;
                r1.w = (v7 - mu) * rs * g1.w + t1.w;
                float* op = &out[(size_t)row * COUT + j0];
                atomicAdd(reinterpret_cast<float4*>(op), r0);
                atomicAdd(reinterpret_cast<float4*>(op + 4), r1);
            }
        }
    }
}

// ---------------------------------------------------------------------------
// Fused s+b edge kernel (COUT=128): per edge computes both MLP+LN outputs and
// scatters ONE combined vector (half the atomics, shared index decode).
__global__ void __launch_bounds__(256, 1)
fused_edgeconv_kernel(const float* __restrict__ Ps, const float* __restrict__ Qs,
                      const float* __restrict__ Pb, const float* __restrict__ Qb,
                      const int* __restrict__ srcC, const int* __restrict__ dstC,
                      const int* __restrict__ dstF,
                      const float* __restrict__ sb1g, const float* __restrict__ sW2g,
                      const float* __restrict__ sb2g, const float* __restrict__ sgg,
                      const float* __restrict__ sbtg,
                      const float* __restrict__ bb1g, const float* __restrict__ bW2g,
                      const float* __restrict__ bb2g, const float* __restrict__ bgg,
                      const float* __restrict__ bbtg,
                      float* __restrict__ out, int NOUT,
                      const int* __restrict__ ncomp) {
    constexpr int COUT = 128;
    constexpr int NE   = 32;
    constexpr int EOFF = 16;
    constexpr int P2   = COUT + 2;
    constexpr int TPE  = 8;
    constexpr int NJG  = 16;
    constexpr int PST  = NJG + 1;
    constexpr int JTU  = 4;
    constexpr int NU   = 4;

    extern __shared__ float sm[];
    float* sW2s = sm;                       // 16384
    float* sW2b = sW2s + COUT * COUT;       // 16384
    float* sb1s = sW2b + COUT * COUT;
    float* sb2s = sb1s + COUT;
    float* sgs  = sb2s + COUT;
    float* sbts = sgs + COUT;
    float* sb1b = sbts + COUT;
    float* sb2b = sb1b + COUT;
    float* sgb  = sb2b + COUT;
    float* sbtb = sgb + COUT;
    float* sF     = sbtb + COUT;            // NE*P2
    float* sPartS = sF + NE * P2;           // NE*PST float2
    float* sPartB = sPartS + NE * PST * 2;  // NE*PST float2
    int*  sdst  = (int*)(sPartB + NE * PST * 2);

    const int tid = threadIdx.x;
    const int ge  = tid / TPE;
    const int sub = tid % TPE;
    const int eh  = tid & (EOFF - 1);
    const int jg  = tid / EOFF;
    const int j0  = jg * 8;

    for (int i = tid; i < (COUT * COUT) / 4; i += 256) {
        reinterpret_cast<float4*>(sW2s)[i] = reinterpret_cast<const float4*>(sW2g)[i];
        reinterpret_cast<float4*>(sW2b)[i] = reinterpret_cast<const float4*>(bW2g)[i];
    }
    if (tid < COUT) {
        sb1s[tid] = sb1g[tid]; sb2s[tid] = sb2g[tid];
        sgs[tid]  = sgg[tid];  sbts[tid] = sbtg[tid];
        sb1b[tid] = bb1g[tid]; sb2b[tid] = bb2g[tid];
        sgb[tid]  = bgg[tid];  sbtb[tid] = bbtg[tid];
    }

    const int Eeff   = *ncomp;
    const int total  = 2 * Eeff;
    const int ntiles = (total + NE - 1) / NE;

    float4 pfP[NU], pfQ[NU];
    int pdst = -1;

    auto fetch = [&](int tile, const float* Pp, const float* Qp) {
        pdst = -1;
        #pragma unroll
        for (int u = 0; u < NU; u++) {
            pfP[u] = make_float4(0.f, 0.f, 0.f, 0.f);
            pfQ[u] = make_float4(0.f, 0.f, 0.f, 0.f);
        }
        int gi = tile * NE + ge;
        if (tile < ntiles && gi < total) {
            int bb = (gi >= Eeff) ? 1 : 0;
            int ee = gi - bb * Eeff;
            int sc = srcC[ee];
            int dc = dstC[ee];
            pdst = bb * NOUT + dstF[ee];
            if (dc >= 0) {
                const float4* pr = reinterpret_cast<const float4*>(
                    Pp + (size_t)(bb * NC + dc) * COUT);
                #pragma unroll
                for (int u = 0; u < NU; u++) pfP[u] = pr[sub + TPE * u];
            }
            if (sc >= 0) {
                const float4* qr = reinterpret_cast<const float4*>(
                    Qp + (size_t)(bb * NC + sc) * COUT);
                #pragma unroll
                for (int u = 0; u < NU; u++) pfQ[u] = qr[sub + TPE * u];
            }
        }
    };

    auto store_h1 = [&](const float* sb1p) {
        float2* frow = reinterpret_cast<float2*>(sF + ge * P2);
        #pragma unroll
        for (int u = 0; u < NU; u++) {
            int c4 = sub + TPE * u;
            float4 b = reinterpret_cast<const float4*>(sb1p)[c4];
            frow[c4 * 2] = make_float2(fmaxf(pfP[u].x + pfQ[u].x + b.x, 0.f),
                                       fmaxf(pfP[u].y + pfQ[u].y + b.y, 0.f));
            frow[c4 * 2 + 1] = make_float2(fmaxf(pfP[u].z + pfQ[u].z + b.z, 0.f),
                                           fmaxf(pfP[u].w + pfQ[u].w + b.w, 0.f));
        }
    };

    auto gemm = [&](const float* sW2p, const float* sb2p, u64* a0, u64* a1) {
        #pragma unroll
        for (int t = 0; t < JTU; t++) {
            u64 bv = *reinterpret_cast<const u64*>(&sb2p[j0 + 2 * t]);
            a0[t] = bv; a1[t] = bv;
        }
        #pragma unroll 2
        for (int k = 0; k < COUT; k += 2) {
            u64 wa[JTU], wb[JTU];
            {
                ulonglong2 t0 = *reinterpret_cast<const ulonglong2*>(&sW2p[k * COUT + j0]);
                ulonglong2 t1 = *reinterpret_cast<const ulonglong2*>(&sW2p[k * COUT + j0 + 4]);
                wa[0] = t0.x; wa[1] = t0.y; wa[2] = t1.x; wa[3] = t1.y;
            }
            {
                ulonglong2 t0 = *reinterpret_cast<const ulonglong2*>(&sW2p[(k + 1) * COUT + j0]);
                ulonglong2 t1 = *reinterpret_cast<const ulonglong2*>(&sW2p[(k + 1) * COUT + j0 + 4]);
                wb[0] = t0.x; wb[1] = t0.y; wb[2] = t1.x; wb[3] = t1.y;
            }
            float2 f0 = *reinterpret_cast<const float2*>(&sF[eh * P2 + k]);
            float2 f1 = *reinterpret_cast<const float2*>(&sF[(eh + EOFF) * P2 + k]);
            u64 x0 = pk2(f0.x), x1 = pk2(f0.y);
            u64 y0 = pk2(f1.x), y1 = pk2(f1.y);
            #pragma unroll
            for (int t = 0; t < JTU; t++) {
                a0[t] = fma2(x0, wa[t], a0[t]);
                a0[t] = fma2(x1, wb[t], a0[t]);
                a1[t] = fma2(y0, wa[t], a1[t]);
                a1[t] = fma2(y1, wb[t], a1[t]);
            }
        }
    };

    auto partials = [&](const u64* a0, const u64* a1, float* sPart) {
        float s0 = 0.f, q0 = 0.f, s1 = 0.f, q1 = 0.f;
        #pragma unroll
        for (int t = 0; t < JTU; t++) {
            float va, vb;
            up2(a0[t], va, vb); s0 += va + vb; q0 += va * va + vb * vb;
            up2(a1[t], va, vb); s1 += va + vb; q1 += va * va + vb * vb;
        }
        float2* pp = reinterpret_cast<float2*>(sPart);
        pp[eh * PST + jg]          = make_float2(s0, q0);
        pp[(eh + EOFF) * PST + jg] = make_float2(s1, q1);
    };

    fetch(blockIdx.x, Ps, Qs);

    for (int tile = blockIdx.x; tile < ntiles; tile += gridDim.x) {
        __syncthreads();  // S1: previous tile fully consumed

        store_h1(sb1s);
        if (sub == 0) sdst[ge] = pdst;
        __syncthreads();  // S2

        fetch(tile, Pb, Qb);  // b gathers hidden under s GEMM

        u64 as0[JTU], as1[JTU];
        gemm(sW2s, sb2s, as0, as1);
        partials(as0, as1, sPartS);
        __syncthreads();  // S3: sF (h1_s) dead, s partials visible

        store_h1(sb1b);
        __syncthreads();  // S4

        fetch(tile + gridDim.x, Ps, Qs);  // next-tile s gathers hidden under b GEMM

        u64 ab0[JTU], ab1v[JTU];
        gemm(sW2b, sb2b, ab0, ab1v);
        partials(ab0, ab1v, sPartB);
        __syncthreads();  // S5

        // ---- combined LN + single atomic scatter ----
        #pragma unroll
        for (int i = 0; i < 2; i++) {
            int e = eh + EOFF * i;
            int row = sdst[e];
            if (row < 0) continue;
            const u64* accs = i ? as1 : as0;
            const u64* accb = i ? ab1v : ab0;
            float ss = 0.f, qs = 0.f, sb = 0.f, qb = 0.f;
            const float2* pps = reinterpret_cast<const float2*>(sPartS) + e * PST;
            const float2* ppb = reinterpret_cast<const float2*>(sPartB) + e * PST;
            #pragma unroll
            for (int t = 0; t < NJG; t++) {
                float2 v1 = pps[t]; ss += v1.x; qs += v1.y;
                float2 v2 = ppb[t]; sb += v2.x; qb += v2.y;
            }
            float mus = ss * (1.f / COUT);
            float rss = rsqrtf(qs * (1.f / COUT) - mus * mus + 1e-5f);
            float mub = sb * (1.f / COUT);
            float rsb = rsqrtf(qb * (1.f / COUT) - mub * mub + 1e-5f);

            float vs[8], vb[8];
            up2(accs[0], vs[0], vs[1]); up2(accs[1], vs[2], vs[3]);
            up2(accs[2], vs[4], vs[5]); up2(accs[3], vs[6], vs[7]);
            up2(accb[0], vb[0], vb[1]); up2(accb[1], vb[2], vb[3]);
            up2(accb[2], vb[4], vb[5]); up2(accb[3], vb[6], vb[7]);

            float r[8];
            #pragma unroll
            for (int t = 0; t < 8; t++) {
                int c = j0 + t;
                r[t] = (vs[t] - mus) * rss * sgs[c] + sbts[c]
                     + (vb[t] - mub) * rsb * sgb[c] + sbtb[c];
            }
            float* op = &out[(size_t)row * COUT + j0];
            atomicAdd(reinterpret_cast<float4*>(op),
                      make_float4(r[0], r[1], r[2], r[3]));
            atomicAdd(reinterpret_cast<float4*>(op + 4),
                      make_float4(r[4], r[5], r[6], r[7]));
        }
    }
}

// ---------------------------------------------------------------------------
// out = leaky_relu(hb + cntA[n]*(cs+cb), 0.01)
__global__ void combine_kernel(float* __restrict__ out, const float* __restrict__ hb,
                               const int* __restrict__ cntA,
                               const float* __restrict__ cs, const float* __restrict__ cb) {
    const int c4n = CO / 4;
    int total = BDIM * NF * c4n;
    int i = blockIdx.x * blockDim.x + threadIdx.x;
    int stride = gridDim.x * blockDim.x;
    for (; i < total; i += stride) {
        int j4 = i % c4n;
        int n  = (i / c4n) % NF;
        float cnt = (float)cntA[n];
        float4 b = reinterpret_cast<const float4*>(hb)[i];
        float4 s = reinterpret_cast<const float4*>(cs)[j4];
        float4 t = reinterpret_cast<const float4*>(cb)[j4];
        float4 r;
        r.x = b.x + cnt * (s.x + t.x); r.x = r.x > 0.f ? r.x : 0.01f * r.x;
        r.y = b.y + cnt * (s.y + t.y); r.y = r.y > 0.f ? r.y : 0.01f * r.y;
        r.z = b.z + cnt * (s.z + t.z); r.z = r.z > 0.f ? r.z : 0.01f * r.z;
        r.w = b.w + cnt * (s.w + t.w); r.w = r.w > 0.f ? r.w : 0.01f * r.w;
        reinterpret_cast<float4*>(out)[i] = r;
    }
}

// ---------------------------------------------------------------------------
static constexpr int fused_smem() {
    int NE = 32, P2 = CO + 2, PST = 17;
    return (2 * CO * CO + 8 * CO + NE * P2 + 2 * NE * PST * 2) * 4 + NE * 4;
}
static constexpr int edge64_smem() {
    int NE = 64, P2 = 66, PST = 9;
    return (64 * 64 + 4 * 64 + NE * P2 + NE * PST * 2) * 4 + NE * 4;
}
static constexpr int ng_smem(int K, int COUT) {
    return (K * COUT + 32 * (K + 1)) * 4;
}

extern "C" void kernel_launch(void* const* d_in, const int* in_sizes, int n_in,
                              void* d_out, int out_size) {
    (void)in_sizes; (void)n_in; (void)out_size;
    const float* x    = (const float*)d_in[0];
    const int*   idx  = (const int*)d_in[1];
    const int*   ei_c = (const int*)d_in[2];
    const int*   ei_f = (const int*)d_in[3];
    const float* sW1 = (const float*)d_in[4];
    const float* sb1 = (const float*)d_in[5];
    const float* sW2 = (const float*)d_in[6];
    const float* sb2 = (const float*)d_in[7];
    const float* sg  = (const float*)d_in[8];
    const float* sbt = (const float*)d_in[9];
    const float* aW1 = (const float*)d_in[10];
    const float* ab1 = (const float*)d_in[11];
    const float* aW2 = (const float*)d_in[12];
    const float* ab2 = (const float*)d_in[13];
    const float* ag  = (const float*)d_in[14];
    const float* abt = (const float*)d_in[15];
    const float* bW1 = (const float*)d_in[16];
    const float* bb1 = (const float*)d_in[17];
    const float* bW2 = (const float*)d_in[18];
    const float* bb2 = (const float*)d_in[19];
    const float* bg  = (const float*)d_in[20];
    const float* bbt = (const float*)d_in[21];
    float* out = (float*)d_out;

    float *hb, *ha, *cs, *cb, *w1s, *w1a, *w1b;
    float *Ps, *Qs, *Pa, *Qa, *Pb, *Qb;
    int *invmap, *cntA, *csrcC, *cdstC, *cdstF;
    cudaGetSymbolAddress((void**)&hb,    g_hb);
    cudaGetSymbolAddress((void**)&ha,    g_ha);
    cudaGetSymbolAddress((void**)&invmap,g_invmap);
    cudaGetSymbolAddress((void**)&cntA,  g_cntA);
    cudaGetSymbolAddress((void**)&csrcC, g_csrcC);
    cudaGetSymbolAddress((void**)&cdstC, g_cdstC);
    cudaGetSymbolAddress((void**)&cdstF, g_cdstF);
    cudaGetSymbolAddress((void**)&cs,    g_cs);
    cudaGetSymbolAddress((void**)&cb,    g_cb);
    cudaGetSymbolAddress((void**)&w1s,   g_w1s);
    cudaGetSymbolAddress((void**)&w1a,   g_w1a);
    cudaGetSymbolAddress((void**)&w1b,   g_w1b);
    cudaGetSymbolAddress((void**)&Ps,    g_Ps);
    cudaGetSymbolAddress((void**)&Qs,    g_Qs);
    cudaGetSymbolAddress((void**)&Pa,    g_Pa);
    cudaGetSymbolAddress((void**)&Qa,    g_Qa);
    cudaGetSymbolAddress((void**)&Pb,    g_Pb);
    cudaGetSymbolAddress((void**)&Qb,    g_Qb);
    int* ncomp = cntA + NF;

    constexpr int FSM  = fused_smem();
    constexpr int ES64 = edge64_smem();
    constexpr int NG_S = ng_smem(128, 128);
    constexpr int NG_A = ng_smem(128, 64);
    constexpr int NG_B = ng_smem(64, 128);
    cudaFuncSetAttribute(fused_edgeconv_kernel,
                         cudaFuncAttributeMaxDynamicSharedMemorySize, FSM);
    cudaFuncSetAttribute(edgeconv64_kernel,
                         cudaFuncAttributeMaxDynamicSharedMemorySize, ES64);
    cudaFuncSetAttribute(nodegemm_kernel<128, 128>,
                         cudaFuncAttributeMaxDynamicSharedMemorySize, NG_S);
    cudaFuncSetAttribute(nodegemm_kernel<128, 64>,
                         cudaFuncAttributeMaxDynamicSharedMemorySize, NG_A);
    cudaFuncSetAttribute(nodegemm_kernel<64, 128>,
                         cudaFuncAttributeMaxDynamicSharedMemorySize, NG_B);

    // Reset state
    zero_kernel<<<512, 256>>>((float4*)hb,  BDIM * NF * CO / 4);
    zero_kernel<<<128, 256>>>((float4*)ha,  BDIM * NC * 64 / 4);
    zero_kernel<<<32, 256>>>((float4*)cntA, (NF + 16) / 4);
    neg1_kernel<<<64, 256>>>((int4*)invmap, NF / 4);

    // Index prep
    invmap_kernel<<<NC / 256, 256>>>(idx, invmap);
    classify_kernel<<<EF / 256, 256>>>(ei_f, invmap, cntA, csrcC, cdstC, cdstF, ncomp);

    // Weight prep + constant vectors
    constvec_kernel<<<1, CO>>>(sb1, sW2, sb2, sg, sbt, cs);
    constvec_kernel<<<1, CO>>>(bb1, bW2, bb2, bg, bbt, cb);
    prepW1_kernel<<<(CI * CO + 255) / 256, 256>>>(sW1, w1s, CI, CO);
    prepW1_kernel<<<(CI * 64 + 255) / 256, 256>>>(aW1, w1a, CI, 64);
    prepW1_kernel<<<(64 * CO + 255) / 256, 256>>>(bW1, w1b, 64, CO);

    // Node GEMMs for s and a (from x)
    nodegemm_kernel<128, 128><<<MROW / 32, 256, NG_S>>>(x, w1s, Ps);
    nodegemm_kernel<128, 128><<<MROW / 32, 256, NG_S>>>(x, w1s + CI * CO, Qs);
    nodegemm_kernel<128, 64><<<MROW / 32, 256, NG_A>>>(x, w1a, Pa);
    nodegemm_kernel<128, 64><<<MROW / 32, 256, NG_A>>>(x, w1a + CI * 64, Qa);

    // a-conv (coarse graph) -> ha
    edgeconv64_kernel<<<296, 256, ES64>>>(
        Pa, Qa, ei_c, ei_c + EC, ab1, aW2, ab2, ag, abt, ha, EC, NC);

    // Node GEMMs for b (from ha)
    nodegemm_kernel<64, 128><<<MROW / 32, 256, NG_B>>>(ha, w1b, Pb);
    nodegemm_kernel<64, 128><<<MROW / 32, 256, NG_B>>>(ha, w1b + 64 * CO, Qb);

    // Fused s+b conv -> hb (one pass, one atomic per edge)
    fused_edgeconv_kernel<<<148, 256, FSM>>>(
        Ps, Qs, Pb, Qb, csrcC, cdstC, cdstF,
        sb1, sW2, sb2, sg, sbt,
        bb1, bW2, bb2, bg, bbt,
        hb, NF, ncomp);

    // out = leaky_relu(hb + cntA*(cs+cb))
    combine_kernel<<<512, 256>>>(out, hb, cntA, cs, cb);
}

// round 7
// speedup vs baseline: 1.1027x; 1.1027x over previous
#include <cuda_runtime.h>
#include <cstdint>

// Problem constants
static constexpr int BDIM = 2;
static constexpr int NC   = 16384;
static constexpr int NF   = 65536;
static constexpr int CI   = 128;
static constexpr int CO   = 128;
static constexpr int EC   = 65536;
static constexpr int EF   = 262144;
static constexpr int MROW = BDIM * NC;   // 32768 coarse rows

// Scratch (device globals)
__device__ float g_hb [(size_t)BDIM * NF * CO];        // s+b conv accumulator
__device__ float g_ha [(size_t)BDIM * NC * (CO / 2)];  // a-conv accumulator
__device__ int   g_invmap[NF];
__device__ int   g_cntA[NF + 16];                      // [NF] = nComp
__device__ int   g_csrcC[EF];
__device__ int   g_cdstC[EF];
__device__ int   g_cdstF[EF];
__device__ float g_cs[CO];
__device__ float g_cb[CO];
__device__ float g_wcs[CI * 2 * CO];                   // Wcat_s [128, 256]
__device__ float g_wca[CI * CO];                       // Wcat_a [128, 128]
__device__ float g_wcb[(CO / 2) * 2 * CO];             // Wcat_b [64, 256]
__device__ float g_Rs[(size_t)MROW * 2 * CO];          // [P_s | Q_s]
__device__ float g_Ra[(size_t)MROW * CO];              // [P_a | Q_a]
__device__ float g_Rb[(size_t)MROW * 2 * CO];          // [P_b | Q_b]

// ---------------------------------------------------------------------------
typedef unsigned long long u64;
__device__ __forceinline__ u64 pk2(float x) {
    u64 r; asm("mov.b64 %0,{%1,%1};" : "=l"(r) : "f"(x)); return r;
}
__device__ __forceinline__ void up2(u64 v, float& x, float& y) {
    asm("mov.b64 {%0,%1},%2;" : "=f"(x), "=f"(y) : "l"(v));
}
__device__ __forceinline__ u64 fma2(u64 a, u64 b, u64 c) {
    u64 d; asm("fma.rn.f32x2 %0,%1,%2,%3;" : "=l"(d) : "l"(a), "l"(b), "l"(c)); return d;
}

// ---------------------------------------------------------------------------
// One kernel: zero hb, ha, cntA; set invmap = -1.
__global__ void init_kernel(float4* __restrict__ hb, float4* __restrict__ ha,
                            int4* __restrict__ cntA, int4* __restrict__ invmap) {
    const int n_hb = BDIM * NF * CO / 4;
    const int n_ha = BDIM * NC * 64 / 4;
    const int n_ct = (NF + 16) / 4;
    const int n_iv = NF / 4;
    const int total = n_hb + n_ha + n_ct + n_iv;
    float4 z = make_float4(0.f, 0.f, 0.f, 0.f);
    int4 zi = make_int4(0, 0, 0, 0);
    int4 mi = make_int4(-1, -1, -1, -1);
    int stride = gridDim.x * blockDim.x;
    for (int i = blockIdx.x * blockDim.x + threadIdx.x; i < total; i += stride) {
        if (i < n_hb) hb[i] = z;
        else if (i < n_hb + n_ha) ha[i - n_hb] = z;
        else if (i < n_hb + n_ha + n_ct) cntA[i - n_hb - n_ha] = zi;
        else invmap[i - n_hb - n_ha - n_ct] = mi;
    }
}

__global__ void invmap_kernel(const int* __restrict__ idx, int* __restrict__ invmap) {
    int i = blockIdx.x * blockDim.x + threadIdx.x;
    if (i < NC) invmap[idx[i]] = i;
}

__global__ void classify_kernel(const int* __restrict__ ei, const int* __restrict__ invmap,
                                int* __restrict__ cntA, int* __restrict__ csrcC,
                                int* __restrict__ cdstC, int* __restrict__ cdstF,
                                int* __restrict__ ncomp) {
    int e = blockIdx.x * blockDim.x + threadIdx.x;
    if (e >= EF) return;
    int s = ei[e], d = ei[EF + e];
    int sc = invmap[s], dc = invmap[d];
    if (sc < 0 && dc < 0) {
        atomicAdd(&cntA[d], 1);
    } else {
        unsigned act = __activemask();
        int lane = threadIdx.x & 31;
        int rank = __popc(act & ((1u << lane) - 1));
        int leader = __ffs(act) - 1;
        int base = 0;
        if (lane == leader) base = atomicAdd(ncomp, __popc(act));
        base = __shfl_sync(act, base, leader);
        csrcC[base + rank] = sc;
        cdstC[base + rank] = dc;
        cdstF[base + rank] = d;
    }
}

// Build all three col-concat weight matrices: Wcat[k, 2C] = [W1a-W1b | W1b]
__global__ void prepWcat_kernel(const float* __restrict__ sW1, const float* __restrict__ aW1,
                                const float* __restrict__ bW1,
                                float* __restrict__ wcs, float* __restrict__ wca,
                                float* __restrict__ wcb) {
    const int n1 = CI * CO;        // s: K=128, C=128
    const int n2 = CI * (CO / 2);  // a: K=128, C=64
    const int n3 = (CO / 2) * CO;  // b: K=64,  C=128
    int i = blockIdx.x * blockDim.x + threadIdx.x;
    if (i < n1) {
        int k = i / CO, j = i % CO;
        float top = sW1[k * CO + j];
        float bot = sW1[(CI + k) * CO + j];
        wcs[k * (2 * CO) + j]      = top - bot;
        wcs[k * (2 * CO) + CO + j] = bot;
    } else if (i < n1 + n2) {
        int ii = i - n1;
        int k = ii / 64, j = ii % 64;
        float top = aW1[k * 64 + j];
        float bot = aW1[(CI + k) * 64 + j];
        wca[k * 128 + j]      = top - bot;
        wca[k * 128 + 64 + j] = bot;
    } else if (i < n1 + n2 + n3) {
        int ii = i - n1 - n2;
        int k = ii / CO, j = ii % CO;
        float top = bW1[k * CO + j];
        float bot = bW1[(64 + k) * CO + j];
        wcb[k * (2 * CO) + j]      = top - bot;
        wcb[k * (2 * CO) + CO + j] = bot;
    }
}

__global__ void constvec_kernel(const float* __restrict__ b1, const float* __restrict__ W2,
                                const float* __restrict__ b2, const float* __restrict__ g,
                                const float* __restrict__ bt, float* __restrict__ c) {
    int j = threadIdx.x;  // CO threads
    float acc = b2[j];
    #pragma unroll 4
    for (int k = 0; k < CO; k++) acc += fmaxf(b1[k], 0.f) * W2[k * CO + j];
    __shared__ float rs_[4], rq_[4];
    float s = acc, qv = acc * acc;
    #pragma unroll
    for (int o = 16; o; o >>= 1) {
        s  += __shfl_xor_sync(0xffffffffu, s, o);
        qv += __shfl_xor_sync(0xffffffffu, qv, o);
    }
    int warp = j >> 5, lane = j & 31;
    if (lane == 0) { rs_[warp] = s; rq_[warp] = qv; }
    __syncthreads();
    float S = 0.f, Q = 0.f;
    #pragma unroll
    for (int w = 0; w < 4; w++) { S += rs_[w]; Q += rq_[w]; }
    float mu  = S * (1.f / CO);
    float var = Q * (1.f / CO) - mu * mu;
    c[j] = (acc - mu) * rsqrtf(var + 1e-5f) * g[j] + bt[j];
}

// ---------------------------------------------------------------------------
// Fused P|Q node GEMM: R[M, CO2] = X[M, K] @ Wcat[K, CO2]. 32 rows per block.
template <int K, int CO2>
__global__ void __launch_bounds__(256)
nodegemmPQ_kernel(const float* __restrict__ X, const float* __restrict__ W,
                  float* __restrict__ R) {
    constexpr int PX  = K + 1;
    constexpr int JT  = CO2 / 8;     // cols per thread (32 or 16)
    constexpr int JT2 = JT / 2;      // u64 accumulators per row (16 or 8)... per 2 rows below
    constexpr int JTT = CO2 / 16;    // cols per thread per row (16 or 8)
    constexpr int JU  = JTT / 2;     // u64 per row (8 or 4)
    constexpr int NXU = K / 32;

    extern __shared__ float sm[];
    float* sW = sm;              // K*CO2
    float* sX = sW + K * CO2;    // 32*PX

    const int tid = threadIdx.x;
    const int m0  = blockIdx.x * 32;

    for (int i = tid; i < (K * CO2) / 4; i += 256)
        reinterpret_cast<float4*>(sW)[i] = reinterpret_cast<const float4*>(W)[i];
    {
        int row = tid >> 3, sub = tid & 7;
        const float4* xr = reinterpret_cast<const float4*>(X + (size_t)(m0 + row) * K);
        #pragma unroll
        for (int u = 0; u < NXU; u++) {
            float4 v = xr[sub + 8 * u];
            float* d = sX + row * PX + (sub + 8 * u) * 4;
            d[0] = v.x; d[1] = v.y; d[2] = v.z; d[3] = v.w;
        }
    }
    __syncthreads();

    const int eh = tid & 15, jg = tid >> 4, j0 = jg * JTT;
    u64 acc[2][JU];
    #pragma unroll
    for (int i = 0; i < 2; i++)
        #pragma unroll
        for (int t = 0; t < JU; t++) acc[i][t] = 0ull;

    #pragma unroll 2
    for (int k = 0; k < K; ++k) {
        u64 w[JU];
        #pragma unroll
        for (int t = 0; t < JU; t += 2) {
            ulonglong2 wv = *reinterpret_cast<const ulonglong2*>(&sW[k * CO2 + j0 + 2 * t]);
            w[t] = wv.x; w[t + 1] = wv.y;
        }
        u64 f0 = pk2(sX[eh * PX + k]);
        u64 f1 = pk2(sX[(eh + 16) * PX + k]);
        #pragma unroll
        for (int t = 0; t < JU; t++) {
            acc[0][t] = fma2(f0, w[t], acc[0][t]);
            acc[1][t] = fma2(f1, w[t], acc[1][t]);
        }
    }

    #pragma unroll
    for (int i = 0; i < 2; i++) {
        float* rr = R + (size_t)(m0 + eh + 16 * i) * CO2 + j0;
        #pragma unroll
        for (int t = 0; t < JU; t += 2) {
            float v0, v1, v2, v3;
            up2(acc[i][t], v0, v1);
            up2(acc[i][t + 1], v2, v3);
            *reinterpret_cast<float4*>(rr + 2 * t) = make_float4(v0, v1, v2, v3);
        }
    }
    (void)JT; (void)JT2;
}

// ---------------------------------------------------------------------------
// Edge kernel (R5-proven): h1 = relu(P[dst]+Q[src]+b1); h2 = h1@W2+b2; LN via
// per-thread partials; atomic float4 scatter from registers. 256 threads.
// P/Q live interleaved in R with row stride 2*COUT (Q = P + COUT).
template <int COUT, bool NCOMP>
__global__ void __launch_bounds__(256, 2)
edgeconv_kernel(const float* __restrict__ R,
                const int* __restrict__ srcC, const int* __restrict__ dstC,
                const int* __restrict__ dstF,
                const float* __restrict__ b1, const float* __restrict__ W2,
                const float* __restrict__ b2, const float* __restrict__ gam,
                const float* __restrict__ bet,
                float* __restrict__ out, int E, int NOUT,
                const int* __restrict__ ncomp) {
    constexpr int LD   = 2 * COUT;
    constexpr int NE   = (COUT == 128) ? 32 : 64;
    constexpr int EOFF = NE / 2;
    constexpr int P2   = COUT + 2;
    constexpr int TPE  = 256 / NE;
    constexpr int NJG  = 256 / EOFF;
    constexpr int PST  = NJG + 1;
    constexpr int JTU  = 4;
    constexpr int NU   = 4;

    extern __shared__ float sm[];
    float* sW2 = sm;
    float* sb1 = sW2 + COUT * COUT;
    float* sb2 = sb1 + COUT;
    float* sg  = sb2 + COUT;
    float* sbt = sg + COUT;
    float* sF  = sbt + COUT;
    float* sPart = sF + NE * P2;
    int*  sdst = (int*)(sPart + NE * PST * 2);

    const int tid = threadIdx.x;
    const int ge  = tid / TPE;
    const int sub = tid % TPE;
    const int eh  = tid & (EOFF - 1);
    const int jg  = tid / EOFF;
    const int j0  = jg * 8;

    for (int i = tid; i < (COUT * COUT) / 4; i += 256)
        reinterpret_cast<float4*>(sW2)[i] = reinterpret_cast<const float4*>(W2)[i];
    if (tid < COUT) {
        sb1[tid] = b1[tid]; sb2[tid] = b2[tid];
        sg[tid]  = gam[tid]; sbt[tid] = bet[tid];
    }

    int Eeff = NCOMP ? *ncomp : E;
    const int total  = 2 * Eeff;
    const int ntiles = (total + NE - 1) / NE;

    float4 pfP[NU], pfQ[NU];
    int pdst = -1;

    auto fetch = [&](int tile) {
        pdst = -1;
        #pragma unroll
        for (int u = 0; u < NU; u++) {
            pfP[u] = make_float4(0.f, 0.f, 0.f, 0.f);
            pfQ[u] = make_float4(0.f, 0.f, 0.f, 0.f);
        }
        int gi = tile * NE + ge;
        if (tile < ntiles && gi < total) {
            int bb = (gi >= Eeff) ? 1 : 0;
            int ee = gi - bb * Eeff;
            int sc = srcC[ee];
            int dc = dstC[ee];
            if (NCOMP) pdst = bb * NOUT + dstF[ee];
            else       pdst = bb * NOUT + dc;
            if (dc >= 0) {
                const float4* pr = reinterpret_cast<const float4*>(
                    R + (size_t)(bb * NC + dc) * LD);
                #pragma unroll
                for (int u = 0; u < NU; u++) pfP[u] = pr[sub + TPE * u];
            }
            if (sc >= 0) {
                const float4* qr = reinterpret_cast<const float4*>(
                    R + (size_t)(bb * NC + sc) * LD + COUT / 4 * 0 + COUT);
                #pragma unroll
                for (int u = 0; u < NU; u++) pfQ[u] = qr[sub + TPE * u];
            }
        }
    };

    fetch(blockIdx.x);

    for (int tile = blockIdx.x; tile < ntiles; tile += gridDim.x) {
        __syncthreads();  // S1

        {
            float2* frow = reinterpret_cast<float2*>(sF + ge * P2);
            #pragma unroll
            for (int u = 0; u < NU; u++) {
                int c4 = sub + TPE * u;
                float4 b = reinterpret_cast<const float4*>(sb1)[c4];
                frow[c4 * 2] = make_float2(fmaxf(pfP[u].x + pfQ[u].x + b.x, 0.f),
                                           fmaxf(pfP[u].y + pfQ[u].y + b.y, 0.f));
                frow[c4 * 2 + 1] = make_float2(fmaxf(pfP[u].z + pfQ[u].z + b.z, 0.f),
                                               fmaxf(pfP[u].w + pfQ[u].w + b.w, 0.f));
            }
            if (sub == 0) sdst[ge] = pdst;
        }
        __syncthreads();  // S2

        fetch(tile + gridDim.x);

        u64 a0[JTU], a1[JTU];
        #pragma unroll
        for (int t = 0; t < JTU; t++) {
            u64 bv = *reinterpret_cast<const u64*>(&sb2[j0 + 2 * t]);
            a0[t] = bv; a1[t] = bv;
        }
        #pragma unroll 4
        for (int k = 0; k < COUT; k += 2) {
            u64 wa[JTU], wb[JTU];
            {
                ulonglong2 t0 = *reinterpret_cast<const ulonglong2*>(&sW2[k * COUT + j0]);
                ulonglong2 t1 = *reinterpret_cast<const ulonglong2*>(&sW2[k * COUT + j0 + 4]);
                wa[0] = t0.x; wa[1] = t0.y; wa[2] = t1.x; wa[3] = t1.y;
            }
            {
                ulonglong2 t0 = *reinterpret_cast<const ulonglong2*>(&sW2[(k + 1) * COUT + j0]);
                ulonglong2 t1 = *reinterpret_cast<const ulonglong2*>(&sW2[(k + 1) * COUT + j0 + 4]);
                wb[0] = t0.x; wb[1] = t0.y; wb[2] = t1.x; wb[3] = t1.y;
            }
            float2 f0 = *reinterpret_cast<const float2*>(&sF[eh * P2 + k]);
            float2 f1 = *reinterpret_cast<const float2*>(&sF[(eh + EOFF) * P2 + k]);
            u64 x0 = pk2(f0.x), x1 = pk2(f0.y);
            u64 y0 = pk2(f1.x), y1 = pk2(f1.y);
            #pragma unroll
            for (int t = 0; t < JTU; t++) {
                a0[t] = fma2(x0, wa[t], a0[t]);
                a0[t] = fma2(x1, wb[t], a0[t]);
                a1[t] = fma2(y0, wa[t], a1[t]);
                a1[t] = fma2(y1, wb[t], a1[t]);
            }
        }

        {
            float s0 = 0.f, q0 = 0.f, s1 = 0.f, q1 = 0.f;
            #pragma unroll
            for (int t = 0; t < JTU; t++) {
                float va, vb;
                up2(a0[t], va, vb); s0 += va + vb; q0 += va * va + vb * vb;
                up2(a1[t], va, vb); s1 += va + vb; q1 += va * va + vb * vb;
            }
            float2* pp = reinterpret_cast<float2*>(sPart);
            pp[eh * PST + jg]          = make_float2(s0, q0);
            pp[(eh + EOFF) * PST + jg] = make_float2(s1, q1);
        }
        __syncthreads();  // S3

        #pragma unroll
        for (int i = 0; i < 2; i++) {
            int e = eh + EOFF * i;
            int row = sdst[e];
            const u64* acc = i ? a1 : a0;
            float s = 0.f, q = 0.f;
            const float2* pp = reinterpret_cast<const float2*>(sPart) + e * PST;
            #pragma unroll
            for (int t = 0; t < NJG; t++) { float2 v = pp[t]; s += v.x; q += v.y; }
            float mu  = s * (1.f / COUT);
            float var = q * (1.f / COUT) - mu * mu;
            float rs  = rsqrtf(var + 1e-5f);
            if (row >= 0) {
                float4 g0 = *reinterpret_cast<const float4*>(sg + j0);
                float4 g1 = *reinterpret_cast<const float4*>(sg + j0 + 4);
                float4 t0 = *reinterpret_cast<const float4*>(sbt + j0);
                float4 t1 = *reinterpret_cast<const float4*>(sbt + j0 + 4);
                float v0, v1, v2, v3, v4, v5, v6, v7;
                up2(acc[0], v0, v1); up2(acc[1], v2, v3);
                up2(acc[2], v4, v5); up2(acc[3], v6, v7);
                float4 r0, r1;
                r0.x = (v0 - mu) * rs * g0.x + t0.x;
                r0.y = (v1 - mu) * rs * g0.y + t0.y;
                r0.z = (v2 - mu) * rs * g0.z + t0.z;
                r0.w = (v3 - mu) * rs * g0.w + t0.w;
                r1.x = (v4 - mu) * rs * g1.x + t1.x;
                r1.y = (v5 - mu) * rs * g1.y + t1.y;
                r1.z = (v6 - mu) * rs * g1.z + t1.z;
                r1.w = (v7 - mu) * rs * g1.w + t1.w;
                float* op = &out[(size_t)row * COUT + j0];
                atomicAdd(reinterpret_cast<float4*>(op), r0);
                atomicAdd(reinterpret_cast<float4*>(op + 4), r1);
            }
        }
    }
}

// ---------------------------------------------------------------------------
// out = leaky_relu(hb + cntA[n]*(cs+cb), 0.01)
__global__ void combine_kernel(float* __restrict__ out, const float* __restrict__ hb,
                               const int* __restrict__ cntA,
                               const float* __restrict__ cs, const float* __restrict__ cb) {
    const int c4n = CO / 4;
    int total = BDIM * NF * c4n;
    int i = blockIdx.x * blockDim.x + threadIdx.x;
    int stride = gridDim.x * blockDim.x;
    for (; i < total; i += stride) {
        int j4 = i % c4n;
        int n  = (i / c4n) % NF;
        float cnt = (float)cntA[n];
        float4 b = reinterpret_cast<const float4*>(hb)[i];
        float4 s = reinterpret_cast<const float4*>(cs)[j4];
        float4 t = reinterpret_cast<const float4*>(cb)[j4];
        float4 r;
        r.x = b.x + cnt * (s.x + t.x); r.x = r.x > 0.f ? r.x : 0.01f * r.x;
        r.y = b.y + cnt * (s.y + t.y); r.y = r.y > 0.f ? r.y : 0.01f * r.y;
        r.z = b.z + cnt * (s.z + t.z); r.z = r.z > 0.f ? r.z : 0.01f * r.z;
        r.w = b.w + cnt * (s.w + t.w); r.w = r.w > 0.f ? r.w : 0.01f * r.w;
        reinterpret_cast<float4*>(out)[i] = r;
    }
}

// ---------------------------------------------------------------------------
static constexpr int edge_smem(int COUT) {
    int NE  = (COUT == 128) ? 32 : 64;
    int NJG = 256 / (NE / 2);
    return (COUT * COUT + 4 * COUT + NE * (COUT + 2) + NE * (NJG + 1) * 2) * 4 + NE * 4;
}
static constexpr int ngpq_smem(int K, int CO2) {
    return (K * CO2 + 32 * (K + 1)) * 4;
}

extern "C" void kernel_launch(void* const* d_in, const int* in_sizes, int n_in,
                              void* d_out, int out_size) {
    (void)in_sizes; (void)n_in; (void)out_size;
    const float* x    = (const float*)d_in[0];
    const int*   idx  = (const int*)d_in[1];
    const int*   ei_c = (const int*)d_in[2];
    const int*   ei_f = (const int*)d_in[3];
    const float* sW1 = (const float*)d_in[4];
    const float* sb1 = (const float*)d_in[5];
    const float* sW2 = (const float*)d_in[6];
    const float* sb2 = (const float*)d_in[7];
    const float* sg  = (const float*)d_in[8];
    const float* sbt = (const float*)d_in[9];
    const float* aW1 = (const float*)d_in[10];
    const float* ab1 = (const float*)d_in[11];
    const float* aW2 = (const float*)d_in[12];
    const float* ab2 = (const float*)d_in[13];
    const float* ag  = (const float*)d_in[14];
    const float* abt = (const float*)d_in[15];
    const float* bW1 = (const float*)d_in[16];
    const float* bb1 = (const float*)d_in[17];
    const float* bW2 = (const float*)d_in[18];
    const float* bb2 = (const float*)d_in[19];
    const float* bg  = (const float*)d_in[20];
    const float* bbt = (const float*)d_in[21];
    float* out = (float*)d_out;

    float *hb, *ha, *cs, *cb, *wcs, *wca, *wcb, *Rs, *Ra, *Rb;
    int *invmap, *cntA, *csrcC, *cdstC, *cdstF;
    cudaGetSymbolAddress((void**)&hb,    g_hb);
    cudaGetSymbolAddress((void**)&ha,    g_ha);
    cudaGetSymbolAddress((void**)&invmap,g_invmap);
    cudaGetSymbolAddress((void**)&cntA,  g_cntA);
    cudaGetSymbolAddress((void**)&csrcC, g_csrcC);
    cudaGetSymbolAddress((void**)&cdstC, g_cdstC);
    cudaGetSymbolAddress((void**)&cdstF, g_cdstF);
    cudaGetSymbolAddress((void**)&cs,    g_cs);
    cudaGetSymbolAddress((void**)&cb,    g_cb);
    cudaGetSymbolAddress((void**)&wcs,   g_wcs);
    cudaGetSymbolAddress((void**)&wca,   g_wca);
    cudaGetSymbolAddress((void**)&wcb,   g_wcb);
    cudaGetSymbolAddress((void**)&Rs,    g_Rs);
    cudaGetSymbolAddress((void**)&Ra,    g_Ra);
    cudaGetSymbolAddress((void**)&Rb,    g_Rb);
    int* ncomp = cntA + NF;

    constexpr int ES128 = edge_smem(128);
    constexpr int ES64  = edge_smem(64);
    constexpr int NG_S  = ngpq_smem(128, 256);  // 147.6 KB
    constexpr int NG_A  = ngpq_smem(128, 128);  // 82 KB
    constexpr int NG_B  = ngpq_smem(64, 256);   // 73.9 KB
    cudaFuncSetAttribute(edgeconv_kernel<128, true>,
                         cudaFuncAttributeMaxDynamicSharedMemorySize, ES128);
    cudaFuncSetAttribute(edgeconv_kernel<64, false>,
                         cudaFuncAttributeMaxDynamicSharedMemorySize, ES64);
    cudaFuncSetAttribute(nodegemmPQ_kernel<128, 256>,
                         cudaFuncAttributeMaxDynamicSharedMemorySize, NG_S);
    cudaFuncSetAttribute(nodegemmPQ_kernel<128, 128>,
                         cudaFuncAttributeMaxDynamicSharedMemorySize, NG_A);
    cudaFuncSetAttribute(nodegemmPQ_kernel<64, 256>,
                         cudaFuncAttributeMaxDynamicSharedMemorySize, NG_B);

    // State reset (one kernel)
    init_kernel<<<640, 256>>>((float4*)hb, (float4*)ha, (int4*)cntA, (int4*)invmap);

    // Index prep
    invmap_kernel<<<NC / 256, 256>>>(idx, invmap);
    classify_kernel<<<EF / 256, 256>>>(ei_f, invmap, cntA, csrcC, cdstC, cdstF, ncomp);

    // Weight prep (one kernel) + constant vectors
    prepWcat_kernel<<<(CI * CO + CI * 64 + 64 * CO + 255) / 256, 256>>>(
        sW1, aW1, bW1, wcs, wca, wcb);
    constvec_kernel<<<1, CO>>>(sb1, sW2, sb2, sg, sbt, cs);
    constvec_kernel<<<1, CO>>>(bb1, bW2, bb2, bg, bbt, cb);

    // Fused P|Q node GEMMs for s and a (from x)
    nodegemmPQ_kernel<128, 256><<<MROW / 32, 256, NG_S>>>(x, wcs, Rs);
    nodegemmPQ_kernel<128, 128><<<MROW / 32, 256, NG_A>>>(x, wca, Ra);

    // a-conv (coarse graph) -> ha
    edgeconv_kernel<64, false><<<296, 256, ES64>>>(
        Ra, ei_c, ei_c + EC, ei_c + EC,
        ab1, aW2, ab2, ag, abt, ha, EC, NC, nullptr);

    // Node GEMM for b (from ha)
    nodegemmPQ_kernel<64, 256><<<MROW / 32, 256, NG_B>>>(ha, wcb, Rb);

    // skip-conv -> hb
    edgeconv_kernel<128, true><<<296, 256, ES128>>>(
        Rs, csrcC, cdstC, cdstF,
        sb1, sW2, sb2, sg, sbt, hb, 0, NF, ncomp);

    // b-conv -> hb (accumulates)
    edgeconv_kernel<128, true><<<296, 256, ES128>>>(
        Rb, csrcC, cdstC, cdstF,
        bb1, bW2, bb2, bg, bbt, hb, 0, NF, ncomp);

    // out = leaky_relu(hb + cntA*(cs+cb))
    combine_kernel<<<512, 256>>>(out, hb, cntA, cs, cb);
}